// round 1
// baseline (speedup 1.0000x reference)
#include <cuda_runtime.h>
#include <cfloat>
#include <math.h>

// CrossFrameAttention: B=4, SAI=9, CK=CV=64, H=W=32
// out[b,c,hw] = softmax_k( Q[b,:,hw]·K[b,:,k] + bias[b,k] ) · V[b,k,:]
// bias = 0 where |dist(b,s)*disp(b,hw_k)| > 0.5 else -inf,  k = s*1024 + hw_k

#define SAI 9
#define NB 4
#define CKD 64
#define HWN 1024
#define CVD 64
#define SHW (SAI * HWN)
#define QT 32
#define KC 128
#define NCHUNK (SHW / KC)   // 72
#define VSTR 130            // padded row stride for Vs (conflict-free reads)
#define PSTR 130

struct __align__(16) Smem {
    float Qsm[CKD][QT];        // Q, c-major: Qsm[c][q]          8 KB
    float Ks[CKD][KC];         // K chunk, k-contiguous          32 KB
    float Vs[CVD][VSTR];       // V chunk, k-contiguous, padded  33.3 KB
    float Ps[QT][PSTR];        // probabilities, k-contiguous    16.6 KB
    float Kp[KC];              // keep flags (0/1) per key
    float Dist[16];            // per-frame distance
    float Sc[QT];              // per-chunk rescale factor per query
    float Lb[QT];              // final softmax denominators
    float2 Obuf[128][16];      // k-half combine buffer          16 KB
};

__device__ __forceinline__ float2 ffma2(float2 a, float2 b, float2 c) {
    float2 d;
    asm("fma.rn.f32x2 %0, %1, %2, %3;"
        : "=l"(reinterpret_cast<unsigned long long &>(d))
        : "l"(reinterpret_cast<unsigned long long &>(a)),
          "l"(reinterpret_cast<unsigned long long &>(b)),
          "l"(reinterpret_cast<unsigned long long &>(c)));
    return d;
}

__global__ __launch_bounds__(256, 1)
void cfa_kernel(const float* __restrict__ gK, const float* __restrict__ gV,
                const float* __restrict__ gQ, const float* __restrict__ gD,
                const int*   __restrict__ gS, float* __restrict__ gO)
{
    extern __shared__ char smraw[];
    Smem* sm = reinterpret_cast<Smem*>(smraw);

    const int b   = blockIdx.y;
    const int hw0 = blockIdx.x * QT;
    const int tid  = threadIdx.x;
    const int lane = tid & 31;
    const int warp = tid >> 5;
    const int qb   = warp * 4;        // QK: this warp owns queries qb..qb+3

    // AV mapping: 2 k-halves x (16 c-groups x 8 q-groups)
    const int kh = tid >> 7;          // k-half
    const int u  = tid & 127;
    const int cg = u & 15;            // c = cg + {0,16,32,48}
    const int qg = u >> 4;
    const int q0 = qg * 4;            // AV: this thread owns queries q0..q0+3

    if (tid < SAI) {
        float x = (float)gS[(b * SAI + tid) * 2 + 0] - 5.f;
        float y = (float)gS[(b * SAI + tid) * 2 + 1] - 5.f;
        sm->Dist[tid] = sqrtf(x * x + y * y);
    }
#pragma unroll
    for (int i = 0; i < 8; i++) {
        int idx = tid + i * 256;
        int c = idx >> 5, q = idx & 31;
        sm->Qsm[c][q] = gQ[(b * CKD + c) * HWN + hw0 + q];
    }

    float mrun[4], lrun[4];
#pragma unroll
    for (int i = 0; i < 4; i++) { mrun[i] = -FLT_MAX; lrun[i] = 0.f; }

    float2 acc[4][4];                 // AV accumulators [q][c], pairs over k
#pragma unroll
    for (int qi = 0; qi < 4; qi++)
#pragma unroll
        for (int ci = 0; ci < 4; ci++) acc[qi][ci] = make_float2(0.f, 0.f);

    const int kA = 2 * lane;          // QK: keys {kA, kA+1, kB, kB+1}
    const int kB = 64 + 2 * lane;

    __syncthreads();

    for (int kc = 0; kc < NCHUNK; kc++) {
        const int s   = kc >> 3;
        const int hwb = (kc & 7) * KC;

        // ---- load K, V chunk + keep flags ----
        const float* kbase = gK + ((size_t)(s * NB + b) * CKD) * HWN + hwb;
        const float* vbase = gV + ((size_t)(s * NB + b) * CVD) * HWN + hwb;
#pragma unroll
        for (int i = 0; i < 8; i++) {
            int idx = tid + i * 256;
            int c  = idx >> 5;
            int k4 = (idx & 31) * 4;
            float4 kv = *reinterpret_cast<const float4*>(kbase + (size_t)c * HWN + k4);
            *reinterpret_cast<float4*>(&sm->Ks[c][k4]) = kv;
            float4 vv = *reinterpret_cast<const float4*>(vbase + (size_t)c * HWN + k4);
            *reinterpret_cast<float2*>(&sm->Vs[c][k4])     = make_float2(vv.x, vv.y);
            *reinterpret_cast<float2*>(&sm->Vs[c][k4 + 2]) = make_float2(vv.z, vv.w);
        }
        if (tid < KC) {
            float d = gD[b * HWN + hwb + tid];
            sm->Kp[tid] = (fabsf(sm->Dist[s] * d) > 0.5f) ? 1.f : 0.f;
        }
        __syncthreads();

        // ---- QK: scores for 4 queries x 4 keys per thread ----
        float2 sa[4], sb[4];
#pragma unroll
        for (int i = 0; i < 4; i++) { sa[i] = make_float2(0.f, 0.f); sb[i] = make_float2(0.f, 0.f); }

#pragma unroll 8
        for (int c = 0; c < CKD; c++) {
            float2 ka  = *reinterpret_cast<const float2*>(&sm->Ks[c][kA]);
            float2 kb2 = *reinterpret_cast<const float2*>(&sm->Ks[c][kB]);
            float4 qv  = *reinterpret_cast<const float4*>(&sm->Qsm[c][qb]);
            float2 d0 = make_float2(qv.x, qv.x);
            float2 d1 = make_float2(qv.y, qv.y);
            float2 d2 = make_float2(qv.z, qv.z);
            float2 d3 = make_float2(qv.w, qv.w);
            sa[0] = ffma2(d0, ka, sa[0]);  sb[0] = ffma2(d0, kb2, sb[0]);
            sa[1] = ffma2(d1, ka, sa[1]);  sb[1] = ffma2(d1, kb2, sb[1]);
            sa[2] = ffma2(d2, ka, sa[2]);  sb[2] = ffma2(d2, kb2, sb[2]);
            sa[3] = ffma2(d3, ka, sa[3]);  sb[3] = ffma2(d3, kb2, sb[3]);
        }

        float2 kpa = *reinterpret_cast<const float2*>(&sm->Kp[kA]);
        float2 kpb = *reinterpret_cast<const float2*>(&sm->Kp[kB]);

        // ---- online softmax (per warp, per query) ----
#pragma unroll
        for (int qq = 0; qq < 4; qq++) {
            float s00 = sa[qq].x, s01 = sa[qq].y, s10 = sb[qq].x, s11 = sb[qq].y;
            float mloc = fmaxf(fmaxf(kpa.x > 0.f ? s00 : -FLT_MAX,
                                     kpa.y > 0.f ? s01 : -FLT_MAX),
                               fmaxf(kpb.x > 0.f ? s10 : -FLT_MAX,
                                     kpb.y > 0.f ? s11 : -FLT_MAX));
#pragma unroll
            for (int off = 16; off > 0; off >>= 1)
                mloc = fmaxf(mloc, __shfl_xor_sync(0xffffffffu, mloc, off));
            float mnew  = fmaxf(mrun[qq], mloc);
            float scale = __expf(mrun[qq] - mnew);
            mrun[qq] = mnew;
            float p00 = kpa.x > 0.f ? __expf(s00 - mnew) : 0.f;
            float p01 = kpa.y > 0.f ? __expf(s01 - mnew) : 0.f;
            float p10 = kpb.x > 0.f ? __expf(s10 - mnew) : 0.f;
            float p11 = kpb.y > 0.f ? __expf(s11 - mnew) : 0.f;
            float ps = (p00 + p01) + (p10 + p11);
#pragma unroll
            for (int off = 16; off > 0; off >>= 1)
                ps += __shfl_xor_sync(0xffffffffu, ps, off);
            lrun[qq] = lrun[qq] * scale + ps;
            *reinterpret_cast<float2*>(&sm->Ps[qb + qq][kA]) = make_float2(p00, p01);
            *reinterpret_cast<float2*>(&sm->Ps[qb + qq][kB]) = make_float2(p10, p11);
            if (lane == 0) sm->Sc[qb + qq] = scale;
        }
        __syncthreads();

        // ---- AV: rescale accumulators, then P·V over this thread's k-half ----
        float sc0 = sm->Sc[q0 + 0], sc1 = sm->Sc[q0 + 1];
        float sc2 = sm->Sc[q0 + 2], sc3 = sm->Sc[q0 + 3];
#pragma unroll
        for (int ci = 0; ci < 4; ci++) {
            acc[0][ci].x *= sc0; acc[0][ci].y *= sc0;
            acc[1][ci].x *= sc1; acc[1][ci].y *= sc1;
            acc[2][ci].x *= sc2; acc[2][ci].y *= sc2;
            acc[3][ci].x *= sc3; acc[3][ci].y *= sc3;
        }
        const int k2base = kh * 32;
#pragma unroll 4
        for (int t = 0; t < 32; t++) {
            int kk = 2 * (k2base + t);
            float2 p0 = *reinterpret_cast<const float2*>(&sm->Ps[q0 + 0][kk]);
            float2 p1 = *reinterpret_cast<const float2*>(&sm->Ps[q0 + 1][kk]);
            float2 p2 = *reinterpret_cast<const float2*>(&sm->Ps[q0 + 2][kk]);
            float2 p3 = *reinterpret_cast<const float2*>(&sm->Ps[q0 + 3][kk]);
            float2 v0 = *reinterpret_cast<const float2*>(&sm->Vs[cg     ][kk]);
            float2 v1 = *reinterpret_cast<const float2*>(&sm->Vs[cg + 16][kk]);
            float2 v2 = *reinterpret_cast<const float2*>(&sm->Vs[cg + 32][kk]);
            float2 v3 = *reinterpret_cast<const float2*>(&sm->Vs[cg + 48][kk]);
            acc[0][0] = ffma2(p0, v0, acc[0][0]);  acc[0][1] = ffma2(p0, v1, acc[0][1]);
            acc[0][2] = ffma2(p0, v2, acc[0][2]);  acc[0][3] = ffma2(p0, v3, acc[0][3]);
            acc[1][0] = ffma2(p1, v0, acc[1][0]);  acc[1][1] = ffma2(p1, v1, acc[1][1]);
            acc[1][2] = ffma2(p1, v2, acc[1][2]);  acc[1][3] = ffma2(p1, v3, acc[1][3]);
            acc[2][0] = ffma2(p2, v0, acc[2][0]);  acc[2][1] = ffma2(p2, v1, acc[2][1]);
            acc[2][2] = ffma2(p2, v2, acc[2][2]);  acc[2][3] = ffma2(p2, v3, acc[2][3]);
            acc[3][0] = ffma2(p3, v0, acc[3][0]);  acc[3][1] = ffma2(p3, v1, acc[3][1]);
            acc[3][2] = ffma2(p3, v2, acc[3][2]);  acc[3][3] = ffma2(p3, v3, acc[3][3]);
        }
        __syncthreads();
    }

    // ---- epilogue: combine k-halves, divide by l, write out ----
    if (lane == 0) {
#pragma unroll
        for (int qq = 0; qq < 4; qq++) sm->Lb[qb + qq] = lrun[qq];
    }
    __syncthreads();
    if (kh == 1) {
#pragma unroll
        for (int qi = 0; qi < 4; qi++)
#pragma unroll
            for (int ci = 0; ci < 4; ci++)
                sm->Obuf[u][qi * 4 + ci] = acc[qi][ci];
    }
    __syncthreads();
    if (kh == 0) {
#pragma unroll
        for (int qi = 0; qi < 4; qi++) {
            float linv = 1.f / sm->Lb[q0 + qi];
#pragma unroll
            for (int ci = 0; ci < 4; ci++) {
                float2 o2 = sm->Obuf[u][qi * 4 + ci];
                float o = ((acc[qi][ci].x + o2.x) + (acc[qi][ci].y + o2.y)) * linv;
                int c = cg + ci * 16;
                gO[((size_t)b * CVD + c) * HWN + hw0 + q0 + qi] = o;
            }
        }
    }
}

extern "C" void kernel_launch(void* const* d_in, const int* in_sizes, int n_in,
                              void* d_out, int out_size)
{
    const float* gK = (const float*)d_in[0];  // memory_keys   (9,4,64,32,32)
    const float* gV = (const float*)d_in[1];  // memory_values (9,4,64,32,32)
    const float* gQ = (const float*)d_in[2];  // query_query   (4,64,32,32)
    const float* gD = (const float*)d_in[3];  // disparity     (4,1,32,32)
    const int*   gS = (const int*)d_in[4];    // sequence_index(4,9,2)
    float* gO = (float*)d_out;                // (4,64,32,32)

    cudaFuncSetAttribute(cfa_kernel, cudaFuncAttributeMaxDynamicSharedMemorySize,
                         (int)sizeof(Smem));
    dim3 grid(HWN / QT, NB);
    cfa_kernel<<<grid, 256, sizeof(Smem)>>>(gK, gV, gQ, gD, gS, gO);
}